// round 12
// baseline (speedup 1.0000x reference)
#include <cuda_runtime.h>
#include <cuda_fp16.h>
#include <math.h>
#include <stdint.h>

// Problem constants
#define E_   2048
#define H_   16
#define D_   128
#define B_   4
#define T_   1024
#define TP_  3072
#define S_   (TP_ + T_)      // 4096
#define NTOK (B_ * T_)       // 4096
#define CACHE_ELEMS (B_ * H_ * S_ * D_)   // 33.5M
#define QSCALE 0.08838834764831845f       // 1/sqrt(128)

// Scratch (device globals -- no allocations allowed)
__device__ __half g_xh[NTOK * E_];     // x in fp16
__device__ __half g_wqh[E_ * E_];
__device__ __half g_wkh[E_ * E_];
__device__ __half g_wvh[E_ * E_];
__device__ __half g_woh[E_ * E_];
__device__ __half g_qh[NTOK * E_];     // Q (scaled) fp16
__device__ __half g_ah[NTOK * E_];     // attention output fp16
__device__ __half g_kh[CACHE_ELEMS];   // K cache shadow fp16 [b,h,s,d]
__device__ __half g_vh[CACHE_ELEMS];   // V cache shadow fp16 [b,h,s,d]

// ---------------------------------------------------------------------------
// Helpers
// ---------------------------------------------------------------------------
__device__ __forceinline__ void mma_f16(float c[4],
    unsigned a0, unsigned a1, unsigned a2, unsigned a3,
    unsigned b0, unsigned b1)
{
    asm volatile(
        "mma.sync.aligned.m16n8k16.row.col.f32.f16.f16.f32 "
        "{%0,%1,%2,%3}, {%4,%5,%6,%7}, {%8,%9}, {%0,%1,%2,%3};"
        : "+f"(c[0]), "+f"(c[1]), "+f"(c[2]), "+f"(c[3])
        : "r"(a0), "r"(a1), "r"(a2), "r"(a3), "r"(b0), "r"(b1));
}

__device__ __forceinline__ unsigned s2u(const void* p) {
    return (unsigned)__cvta_generic_to_shared(p);
}

__device__ __forceinline__ unsigned h2u(float x, float y) {
    __half2 h = __floats2half2_rn(x, y);
    return *(unsigned*)&h;
}

#define CP16(dst_u32, src_ptr) \
    asm volatile("cp.async.cg.shared.global [%0], [%1], 16;" :: "r"(dst_u32), "l"(src_ptr))
#define CP_COMMIT() asm volatile("cp.async.commit_group;")
#define CP_WAIT0()  asm volatile("cp.async.wait_group 0;")
#define CP_WAIT1()  asm volatile("cp.async.wait_group 1;")

__device__ __forceinline__ void ldm_x4(unsigned r[4], unsigned addr) {
    asm volatile(
        "ldmatrix.sync.aligned.m8n8.x4.shared.b16 {%0,%1,%2,%3}, [%4];"
        : "=r"(r[0]), "=r"(r[1]), "=r"(r[2]), "=r"(r[3]) : "r"(addr));
}

__device__ __forceinline__ void ldm_x4_trans(unsigned r[4], unsigned addr) {
    asm volatile(
        "ldmatrix.sync.aligned.m8n8.x4.trans.shared.b16 {%0,%1,%2,%3}, [%4];"
        : "=r"(r[0]), "=r"(r[1]), "=r"(r[2]), "=r"(r[3]) : "r"(addr));
}

// ---------------------------------------------------------------------------
// Fused fp32 -> fp16 conversion (x + 4 weights in one launch)
// ---------------------------------------------------------------------------
__global__ void to_half_all(const float* __restrict__ x,
                            const float* __restrict__ wq,
                            const float* __restrict__ wk,
                            const float* __restrict__ wv,
                            const float* __restrict__ wo)
{
    const int z = blockIdx.y;
    const float* src = (z == 0) ? x : (z == 1) ? wq : (z == 2) ? wk
                      : (z == 3) ? wv : wo;
    __half* dst = (z == 0) ? g_xh : (z == 1) ? g_wqh : (z == 2) ? g_wkh
                 : (z == 3) ? g_wvh : g_woh;
    const int n4 = (z == 0) ? NTOK * E_ / 4 : E_ * E_ / 4;
    for (int i = blockIdx.x * blockDim.x + threadIdx.x; i < n4;
         i += gridDim.x * blockDim.x) {
        float4 v = ((const float4*)src)[i];
        uint2 u = { h2u(v.x, v.y), h2u(v.z, v.w) };
        ((uint2*)dst)[i] = u;
    }
}

// ---------------------------------------------------------------------------
// fp16 tensor-core GEMM + fused past-KV copy. 2-stage cp.async +
// fragment software pipeline across ks (all 6 ldmatrix of ks+1 issued
// before the 16 MMAs of ks).
// mode = base_mode + blockIdx.z:
//   0=Q-proj, 1=K-proj, 2=V-proj, 3=past-KV copy, 4=O-proj.
// ---------------------------------------------------------------------------
#define GAP 72
#define HA  (128 * GAP)         // halfs per buffer (9216)
#define GEMM_SMEM (4 * HA * 2)  // 73728 bytes

__global__ __launch_bounds__(256, 2) void gemm_h(
    int base_mode,
    const float* __restrict__ bq, const float* __restrict__ bk,
    const float* __restrict__ bv, const float* __restrict__ bo,
    const float* __restrict__ past_k, const float* __restrict__ past_v,
    float* __restrict__ kc, float* __restrict__ vc, float* __restrict__ outp)
{
    const int mode = base_mode + blockIdx.z;

    if (mode == 3) {
        // ---- past copy CTAs (grid-stride over float4s) ----
        const int total4 = B_ * H_ * TP_ * D_ / 4;
        const int nct = gridDim.x * gridDim.y;
        const int cta = blockIdx.y * gridDim.x + blockIdx.x;
        for (int idx = cta * 256 + threadIdx.x; idx < total4; idx += nct * 256) {
            int bh  = idx / (TP_ * D_ / 4);
            int off = (idx % (TP_ * D_ / 4)) * 4;
            size_t dst = (size_t)bh * S_ * D_ + off;
            float4 kv = *(const float4*)&past_k[(size_t)idx * 4];
            float4 vv = *(const float4*)&past_v[(size_t)idx * 4];
            *(float4*)&kc[dst] = kv;
            *(float4*)&vc[dst] = vv;
            uint2 kh = { h2u(kv.x, kv.y), h2u(kv.z, kv.w) };
            uint2 vh = { h2u(vv.x, vv.y), h2u(vv.z, vv.w) };
            *(uint2*)&g_kh[dst] = kh;
            *(uint2*)&g_vh[dst] = vh;
        }
        return;
    }

    extern __shared__ __half sh[];
    __half* bufA[2] = { sh,      sh + 2 * HA };
    __half* bufB[2] = { sh + HA, sh + 3 * HA };

    const __half* A    = (mode < 3) ? g_xh : g_ah;
    const __half* W    = (mode == 0) ? g_wqh : (mode == 1) ? g_wkh
                        : (mode == 2) ? g_wvh : g_woh;
    const float* bias  = (mode == 0) ? bq : (mode == 1) ? bk
                        : (mode == 2) ? bv : bo;

    const int tid  = threadIdx.x;
    const int lane = tid & 31, wid = tid >> 5;
    const int wm = wid >> 1, wn = wid & 1;
    const int g = lane >> 2, t = lane & 3;
    const int brow = blockIdx.y * 128, bcol = blockIdx.x * 128;

    const unsigned lmo = (((lane & 15) * GAP) + (lane >> 4) * 8) * 2;  // bytes

    float acc[2][8][4];
#pragma unroll
    for (int mi = 0; mi < 2; mi++)
#pragma unroll
        for (int nj = 0; nj < 8; nj++)
#pragma unroll
            for (int q = 0; q < 4; q++) acc[mi][nj][q] = 0.f;

    // prologue: buffer 0 (k0 = 0)
#pragma unroll
    for (int l = 0; l < 4; l++) {
        int idx = tid + l * 256;
        int r = idx >> 3, c = (idx & 7) * 8;
        CP16(s2u(&bufA[0][r * GAP + c]), &A[(size_t)(brow + r) * E_ + c]);
        CP16(s2u(&bufB[0][r * GAP + c]), &W[(size_t)(bcol + r) * E_ + c]);
    }
    CP_COMMIT();

    const int KT = E_ / 64;  // 32
    for (int kt = 0; kt < KT; kt++) {
        const int cur = kt & 1;
        CP_WAIT0();
        __syncthreads();
        if (kt + 1 < KT) {
            const int k0 = (kt + 1) * 64;
#pragma unroll
            for (int l = 0; l < 4; l++) {
                int idx = tid + l * 256;
                int r = idx >> 3, c = (idx & 7) * 8;
                CP16(s2u(&bufA[cur ^ 1][r * GAP + c]), &A[(size_t)(brow + r) * E_ + k0 + c]);
                CP16(s2u(&bufB[cur ^ 1][r * GAP + c]), &W[(size_t)(bcol + r) * E_ + k0 + c]);
            }
            CP_COMMIT();
        }

        const unsigned aBase = s2u(bufA[cur]) + (unsigned)(wm * 32 * GAP * 2) + lmo;
        const unsigned bBase = s2u(bufB[cur]) + (unsigned)(wn * 64 * GAP * 2) + lmo;

        // fragment pipeline: load ks frags into slot ks&1; prefetch ks+1
        unsigned aF[2][2][4], bF[2][4][4];
        ldm_x4(aF[0][0], aBase);
        ldm_x4(aF[0][1], aBase + 16 * GAP * 2);
#pragma unroll
        for (int njp = 0; njp < 4; njp++)
            ldm_x4(bF[0][njp], bBase + njp * 16 * GAP * 2);

#pragma unroll
        for (int ks = 0; ks < 4; ks++) {
            const int cb = ks & 1;
            if (ks < 3) {
                const unsigned koff = (ks + 1) * 32;
                ldm_x4(aF[cb ^ 1][0], aBase + koff);
                ldm_x4(aF[cb ^ 1][1], aBase + 16 * GAP * 2 + koff);
#pragma unroll
                for (int njp = 0; njp < 4; njp++)
                    ldm_x4(bF[cb ^ 1][njp], bBase + njp * 16 * GAP * 2 + koff);
            }
#pragma unroll
            for (int njp = 0; njp < 4; njp++) {
                mma_f16(acc[0][2 * njp],     aF[cb][0][0], aF[cb][0][1], aF[cb][0][2], aF[cb][0][3],
                        bF[cb][njp][0], bF[cb][njp][2]);
                mma_f16(acc[0][2 * njp + 1], aF[cb][0][0], aF[cb][0][1], aF[cb][0][2], aF[cb][0][3],
                        bF[cb][njp][1], bF[cb][njp][3]);
                mma_f16(acc[1][2 * njp],     aF[cb][1][0], aF[cb][1][1], aF[cb][1][2], aF[cb][1][3],
                        bF[cb][njp][0], bF[cb][njp][2]);
                mma_f16(acc[1][2 * njp + 1], aF[cb][1][0], aF[cb][1][1], aF[cb][1][2], aF[cb][1][3],
                        bF[cb][njp][1], bF[cb][njp][3]);
            }
        }
    }
    __syncthreads();

    // epilogue
#pragma unroll
    for (int mi = 0; mi < 2; mi++) {
#pragma unroll
        for (int nj = 0; nj < 8; nj++) {
            int row = brow + wm * 32 + mi * 16 + g;
            int col = bcol + wn * 64 + nj * 8 + 2 * t;
            float b0 = bias[col], b1 = bias[col + 1];
            float v00 = acc[mi][nj][0] + b0, v01 = acc[mi][nj][1] + b1;
            float v10 = acc[mi][nj][2] + b0, v11 = acc[mi][nj][3] + b1;
            if (mode == 0) {
                *(unsigned*)&g_qh[(size_t)row * E_ + col] =
                    h2u(v00 * QSCALE, v01 * QSCALE);
                *(unsigned*)&g_qh[(size_t)(row + 8) * E_ + col] =
                    h2u(v10 * QSCALE, v11 * QSCALE);
            } else if (mode == 4) {
                float2 f0 = { v00, v01 }, f1 = { v10, v11 };
                *(float2*)&outp[(size_t)row * E_ + col]       = f0;
                *(float2*)&outp[(size_t)(row + 8) * E_ + col] = f1;
            } else {
                float* dst   = (mode == 1) ? kc  : vc;
                __half* dstH = (mode == 1) ? g_kh : g_vh;
                int b_i = row >> 10, t_i = row & 1023;
                int h_i = col >> 7,  d_i = col & 127;
                size_t base = ((size_t)(b_i * H_ + h_i) * S_ + TP_ + t_i) * D_ + d_i;
                float2 f0 = { v00, v01 }, f1 = { v10, v11 };
                *(float2*)&dst[base]             = f0;
                *(float2*)&dst[base + 8ull * D_] = f1;
                *(unsigned*)&dstH[base]             = h2u(v00, v01);
                *(unsigned*)&dstH[base + 8ull * D_] = h2u(v10, v11);
            }
        }
    }
}

// ---------------------------------------------------------------------------
// fp16 tensor-core flash attention.
// K and V double-buffered in one cp.async group, ONE __syncthreads per chunk.
// P stays in registers. QK a-fragments prefetched across ks.
// ---------------------------------------------------------------------------
#define QPH 136
#define KPH 136
#define VPH 136
#define ATTN_SMEM ((128*QPH + 2*64*KPH + 2*64*VPH) * 2)   // 104448 bytes

__global__ __launch_bounds__(256, 2) void attn_h(void)
{
    extern __shared__ __half sm[];
    __half* sQ = sm;                         // 128 x 136
    __half* sK = sQ + 128 * QPH;             // 2 x 64 x 136
    __half* sV = sK + 2 * 64 * KPH;          // 2 x 64 x 136

    const int qt = blockIdx.x, h = blockIdx.y, b = blockIdx.z;
    const int tid = threadIdx.x, lane = tid & 31, w = tid >> 5;

    const __half* kb = g_kh + (size_t)(b * H_ + h) * S_ * D_;
    const __half* vb = g_vh + (size_t)(b * H_ + h) * S_ * D_;

    // prologue: prefetch K0 + V0 in one group
#pragma unroll
    for (int l = 0; l < 4; l++) {
        int idx = tid + l * 256;
        int r = idx >> 4, c = (idx & 15) * 8;
        CP16(s2u(&sK[r * KPH + c]), &kb[(size_t)r * D_ + c]);
        CP16(s2u(&sV[r * VPH + c]), &vb[(size_t)r * D_ + c]);
    }
    CP_COMMIT();

    // stage Q tile (fp16, already scaled)
#pragma unroll
    for (int l = 0; l < 8; l++) {
        int idx = tid + l * 256;
        int r = idx >> 4, c = (idx & 15) * 8;
        uint4 qv = *(const uint4*)&g_qh[(size_t)(b * T_ + qt * 128 + r) * E_ + h * D_ + c];
        *(uint4*)&sQ[r * QPH + c] = qv;
    }

    float m0 = -1e30f, m1 = -1e30f, l0 = 0.f, l1 = 0.f;
    float acc_o[16][4];
#pragma unroll
    for (int nj = 0; nj < 16; nj++)
#pragma unroll
        for (int q = 0; q < 4; q++) acc_o[nj][q] = 0.f;

    const unsigned lmoQ = (((lane & 15) * QPH) + (lane >> 4) * 8) * 2;
    const unsigned lmoK = (((lane & 15) * KPH) + (lane >> 4) * 8) * 2;
    const unsigned aQBase = s2u(sQ) + (unsigned)(w * 16 * QPH * 2) + lmoQ;

    for (int ci = 0; ci < S_ / 64; ci++) {
        const int cur = ci & 1;
        const unsigned bKBase = s2u(sK + cur * 64 * KPH) + lmoK;
        __half* cV = sV + cur * 64 * VPH;

        CP_WAIT0();
        __syncthreads();   // chunk ci resident; all warps done with ci-1 buffers

        // prefetch K_{ci+1} + V_{ci+1} into the freed buffers
        if (ci + 1 < S_ / 64) {
            const size_t nbase = (size_t)((ci + 1) * 64) * D_;
            __half* nK = sK + (cur ^ 1) * 64 * KPH;
            __half* nV = sV + (cur ^ 1) * 64 * VPH;
#pragma unroll
            for (int l = 0; l < 4; l++) {
                int idx = tid + l * 256;
                int r = idx >> 4, c = (idx & 15) * 8;
                CP16(s2u(&nK[r * KPH + c]), &kb[nbase + (size_t)r * D_ + c]);
                CP16(s2u(&nV[r * VPH + c]), &vb[nbase + (size_t)r * D_ + c]);
            }
            CP_COMMIT();
        }

        // S = Q K^T   (warp: 16 q-rows x 64 keys, 8 k-steps)
        float accs[8][4];
#pragma unroll
        for (int nj = 0; nj < 8; nj++)
#pragma unroll
            for (int q = 0; q < 4; q++) accs[nj][q] = 0.f;

        unsigned aF[2][4];
        ldm_x4(aF[0], aQBase);
#pragma unroll
        for (int ks = 0; ks < 8; ks++) {
            const int cb = ks & 1;
            if (ks < 7) ldm_x4(aF[cb ^ 1], aQBase + (ks + 1) * 32);
            const unsigned koff = ks * 32;
            unsigned bfr[2][4];
            ldm_x4(bfr[0], bKBase + koff);
#pragma unroll
            for (int njp = 0; njp < 4; njp++) {
                const int c2 = njp & 1;
                if (njp < 3)
                    ldm_x4(bfr[c2 ^ 1], bKBase + (njp + 1) * 16 * KPH * 2 + koff);
                mma_f16(accs[2 * njp],     aF[cb][0], aF[cb][1], aF[cb][2], aF[cb][3],
                        bfr[c2][0], bfr[c2][2]);
                mma_f16(accs[2 * njp + 1], aF[cb][0], aF[cb][1], aF[cb][2], aF[cb][3],
                        bfr[c2][1], bfr[c2][3]);
            }
        }

        // online softmax
        float rm0 = -1e30f, rm1 = -1e30f;
#pragma unroll
        for (int nj = 0; nj < 8; nj++) {
            rm0 = fmaxf(rm0, fmaxf(accs[nj][0], accs[nj][1]));
            rm1 = fmaxf(rm1, fmaxf(accs[nj][2], accs[nj][3]));
        }
        rm0 = fmaxf(rm0, __shfl_xor_sync(0xffffffffu, rm0, 1));
        rm0 = fmaxf(rm0, __shfl_xor_sync(0xffffffffu, rm0, 2));
        rm1 = fmaxf(rm1, __shfl_xor_sync(0xffffffffu, rm1, 1));
        rm1 = fmaxf(rm1, __shfl_xor_sync(0xffffffffu, rm1, 2));

        float nm0 = fmaxf(m0, rm0), nm1 = fmaxf(m1, rm1);
        float al0 = __expf(m0 - nm0), al1 = __expf(m1 - nm1);
        m0 = nm0; m1 = nm1;

        unsigned pA[8], pB[8];
        float sum0 = 0.f, sum1 = 0.f;
#pragma unroll
        for (int nj = 0; nj < 8; nj++) {
            float p0 = __expf(accs[nj][0] - nm0);
            float p1 = __expf(accs[nj][1] - nm0);
            float p2 = __expf(accs[nj][2] - nm1);
            float p3 = __expf(accs[nj][3] - nm1);
            sum0 += p0 + p1;
            sum1 += p2 + p3;
            pA[nj] = h2u(p0, p1);
            pB[nj] = h2u(p2, p3);
        }
        sum0 += __shfl_xor_sync(0xffffffffu, sum0, 1);
        sum0 += __shfl_xor_sync(0xffffffffu, sum0, 2);
        sum1 += __shfl_xor_sync(0xffffffffu, sum1, 1);
        sum1 += __shfl_xor_sync(0xffffffffu, sum1, 2);
        l0 = l0 * al0 + sum0;
        l1 = l1 * al1 + sum1;

        if (!__all_sync(0xffffffffu, (al0 == 1.f) && (al1 == 1.f))) {
#pragma unroll
            for (int nj = 0; nj < 16; nj++) {
                acc_o[nj][0] *= al0; acc_o[nj][1] *= al0;
                acc_o[nj][2] *= al1; acc_o[nj][3] *= al1;
            }
        }

        // O += P V   (V already resident; no extra wait/sync)
#pragma unroll
        for (int ks = 0; ks < 4; ks++) {
            const unsigned a0 = pA[2 * ks],     a1 = pB[2 * ks];
            const unsigned a2 = pA[2 * ks + 1], a3 = pB[2 * ks + 1];
            int key = ks * 16 + (lane & 15);
            unsigned bb[2][4];
            ldm_x4_trans(bb[0], s2u(&cV[key * VPH + (lane >> 4) * 8]));
#pragma unroll
            for (int nj2 = 0; nj2 < 8; nj2++) {
                const int c2 = nj2 & 1;
                if (nj2 < 7) {
                    int dd = (nj2 + 1) * 16 + (lane >> 4) * 8;
                    ldm_x4_trans(bb[c2 ^ 1], s2u(&cV[key * VPH + dd]));
                }
                mma_f16(acc_o[nj2 * 2],     a0, a1, a2, a3, bb[c2][0], bb[c2][1]);
                mma_f16(acc_o[nj2 * 2 + 1], a0, a1, a2, a3, bb[c2][2], bb[c2][3]);
            }
        }
    }

    // epilogue: normalize, write fp16 to g_ah
    const int g = lane >> 2, t = lane & 3;
    float inv0 = 1.f / l0, inv1 = 1.f / l1;
    int row = b * T_ + qt * 128 + w * 16 + g;
#pragma unroll
    for (int nj = 0; nj < 16; nj++) {
        int col = h * D_ + nj * 8 + 2 * t;
        *(unsigned*)&g_ah[(size_t)row * E_ + col] =
            h2u(acc_o[nj][0] * inv0, acc_o[nj][1] * inv0);
        *(unsigned*)&g_ah[(size_t)(row + 8) * E_ + col] =
            h2u(acc_o[nj][2] * inv1, acc_o[nj][3] * inv1);
    }
}

// ---------------------------------------------------------------------------
extern "C" void kernel_launch(void* const* d_in, const int* in_sizes, int n_in,
                              void* d_out, int out_size)
{
    const float* x      = (const float*)d_in[0];
    const float* past_k = (const float*)d_in[1];
    const float* past_v = (const float*)d_in[2];
    const float* Wq     = (const float*)d_in[3];
    const float* bq     = (const float*)d_in[4];
    const float* Wk     = (const float*)d_in[5];
    const float* bk     = (const float*)d_in[6];
    const float* Wv     = (const float*)d_in[7];
    const float* bv     = (const float*)d_in[8];
    const float* Wo     = (const float*)d_in[9];
    const float* bo     = (const float*)d_in[10];

    float* out = (float*)d_out;                       // [B,T,E]
    float* kc  = out + (size_t)NTOK * E_;             // [B,H,S,D]
    float* vc  = kc + (size_t)CACHE_ELEMS;            // [B,H,S,D]

    // fp32 -> fp16 conversions (single launch)
    to_half_all<<<dim3(512, 5), 256>>>(x, Wq, Wk, Wv, Wo);

    cudaFuncSetAttribute(gemm_h, cudaFuncAttributeMaxDynamicSharedMemorySize, GEMM_SMEM);
    cudaFuncSetAttribute(attn_h, cudaFuncAttributeMaxDynamicSharedMemorySize, ATTN_SMEM);

    // fused QKV projections (z=0..2) + past-KV copy (z=3) in one launch
    dim3 gq(E_ / 128, NTOK / 128, 4);
    gemm_h<<<gq, 256, GEMM_SMEM>>>(0, bq, bk, bv, bo, past_k, past_v,
                                   kc, vc, out);

    // attention
    attn_h<<<dim3(T_ / 128, H_, B_), 256, ATTN_SMEM>>>();

    // output projection (mode 4)
    dim3 go(E_ / 128, NTOK / 128, 1);
    gemm_h<<<go, 256, GEMM_SMEM>>>(4, bq, bk, bv, bo, past_k, past_v,
                                   kc, vc, out);
}

// round 13
// speedup vs baseline: 1.0515x; 1.0515x over previous
#include <cuda_runtime.h>
#include <cuda_fp16.h>
#include <math.h>
#include <stdint.h>

// Problem constants
#define E_   2048
#define H_   16
#define D_   128
#define B_   4
#define T_   1024
#define TP_  3072
#define S_   (TP_ + T_)      // 4096
#define NTOK (B_ * T_)       // 4096
#define CACHE_ELEMS (B_ * H_ * S_ * D_)   // 33.5M
#define QSCALE 0.08838834764831845f       // 1/sqrt(128)

// Scratch (device globals -- no allocations allowed)
__device__ __half g_xh[NTOK * E_];     // x in fp16
__device__ __half g_wqh[E_ * E_];
__device__ __half g_wkh[E_ * E_];
__device__ __half g_wvh[E_ * E_];
__device__ __half g_woh[E_ * E_];
__device__ __half g_qh[NTOK * E_];     // Q (scaled) fp16
__device__ __half g_ah[NTOK * E_];     // attention output fp16
__device__ __half g_kh[CACHE_ELEMS];   // K cache shadow fp16 [b,h,s,d]
__device__ __half g_vh[CACHE_ELEMS];   // V cache shadow fp16 [b,h,s,d]

// ---------------------------------------------------------------------------
// Helpers
// ---------------------------------------------------------------------------
__device__ __forceinline__ void mma_f16(float c[4],
    unsigned a0, unsigned a1, unsigned a2, unsigned a3,
    unsigned b0, unsigned b1)
{
    asm volatile(
        "mma.sync.aligned.m16n8k16.row.col.f32.f16.f16.f32 "
        "{%0,%1,%2,%3}, {%4,%5,%6,%7}, {%8,%9}, {%0,%1,%2,%3};"
        : "+f"(c[0]), "+f"(c[1]), "+f"(c[2]), "+f"(c[3])
        : "r"(a0), "r"(a1), "r"(a2), "r"(a3), "r"(b0), "r"(b1));
}

__device__ __forceinline__ unsigned s2u(const void* p) {
    return (unsigned)__cvta_generic_to_shared(p);
}

__device__ __forceinline__ unsigned h2u(float x, float y) {
    __half2 h = __floats2half2_rn(x, y);
    return *(unsigned*)&h;
}

#define CP16(dst_u32, src_ptr) \
    asm volatile("cp.async.cg.shared.global [%0], [%1], 16;" :: "r"(dst_u32), "l"(src_ptr))
#define CP_COMMIT() asm volatile("cp.async.commit_group;")
#define CP_WAIT0()  asm volatile("cp.async.wait_group 0;")
#define CP_WAIT1()  asm volatile("cp.async.wait_group 1;")

__device__ __forceinline__ void ldm_x4(unsigned r[4], unsigned addr) {
    asm volatile(
        "ldmatrix.sync.aligned.m8n8.x4.shared.b16 {%0,%1,%2,%3}, [%4];"
        : "=r"(r[0]), "=r"(r[1]), "=r"(r[2]), "=r"(r[3]) : "r"(addr));
}

__device__ __forceinline__ void ldm_x4_trans(unsigned r[4], unsigned addr) {
    asm volatile(
        "ldmatrix.sync.aligned.m8n8.x4.trans.shared.b16 {%0,%1,%2,%3}, [%4];"
        : "=r"(r[0]), "=r"(r[1]), "=r"(r[2]), "=r"(r[3]) : "r"(addr));
}

// ---------------------------------------------------------------------------
// Fused fp32 -> fp16 conversion (x + 4 weights in one launch)
// ---------------------------------------------------------------------------
__global__ void to_half_all(const float* __restrict__ x,
                            const float* __restrict__ wq,
                            const float* __restrict__ wk,
                            const float* __restrict__ wv,
                            const float* __restrict__ wo)
{
    const int z = blockIdx.y;
    const float* src = (z == 0) ? x : (z == 1) ? wq : (z == 2) ? wk
                      : (z == 3) ? wv : wo;
    __half* dst = (z == 0) ? g_xh : (z == 1) ? g_wqh : (z == 2) ? g_wkh
                 : (z == 3) ? g_wvh : g_woh;
    const int n4 = (z == 0) ? NTOK * E_ / 4 : E_ * E_ / 4;
    for (int i = blockIdx.x * blockDim.x + threadIdx.x; i < n4;
         i += gridDim.x * blockDim.x) {
        float4 v = ((const float4*)src)[i];
        uint2 u = { h2u(v.x, v.y), h2u(v.z, v.w) };
        ((uint2*)dst)[i] = u;
    }
}

// ---------------------------------------------------------------------------
// fp16 tensor-core GEMM + fused past-KV copy. FLAT 1-D grid with INTERLEAVED
// copy CTAs:  base_mode==0: mode = cid & 3 (0=Q,1=K,2=V,3=copy), tile = cid>>2.
//             base_mode==4: mode = 4 (O-proj), tile = cid.
// Copy CTAs are spread evenly through the schedule so the DRAM-bound past-KV
// copy overlaps the tensor-bound GEMM waves instead of trailing them.
// ---------------------------------------------------------------------------
#define GAP 72
#define HA  (128 * GAP)         // halfs per buffer (9216)
#define GEMM_SMEM (4 * HA * 2)  // 73728 bytes
#define NCOPY 512               // copy slices

__global__ __launch_bounds__(256, 2) void gemm_h(
    int base_mode,
    const float* __restrict__ bq, const float* __restrict__ bk,
    const float* __restrict__ bv, const float* __restrict__ bo,
    const float* __restrict__ past_k, const float* __restrict__ past_v,
    float* __restrict__ kc, float* __restrict__ vc, float* __restrict__ outp)
{
    const int cid = blockIdx.x;
    int mode, tile;
    if (base_mode == 0) { mode = cid & 3; tile = cid >> 2; }
    else                { mode = 4;       tile = cid;      }

    if (mode == 3) {
        // ---- past copy CTA (slice `tile` of NCOPY, strided over float4s) ----
        const int total4 = B_ * H_ * TP_ * D_ / 4;
        for (int idx = tile * 256 + threadIdx.x; idx < total4; idx += NCOPY * 256) {
            int bh  = idx / (TP_ * D_ / 4);
            int off = (idx % (TP_ * D_ / 4)) * 4;
            size_t dst = (size_t)bh * S_ * D_ + off;
            float4 kv = *(const float4*)&past_k[(size_t)idx * 4];
            float4 vv = *(const float4*)&past_v[(size_t)idx * 4];
            *(float4*)&kc[dst] = kv;
            *(float4*)&vc[dst] = vv;
            uint2 kh = { h2u(kv.x, kv.y), h2u(kv.z, kv.w) };
            uint2 vh = { h2u(vv.x, vv.y), h2u(vv.z, vv.w) };
            *(uint2*)&g_kh[dst] = kh;
            *(uint2*)&g_vh[dst] = vh;
        }
        return;
    }

    extern __shared__ __half sh[];
    __half* bufA[2] = { sh,      sh + 2 * HA };
    __half* bufB[2] = { sh + HA, sh + 3 * HA };

    const __half* A    = (mode < 3) ? g_xh : g_ah;
    const __half* W    = (mode == 0) ? g_wqh : (mode == 1) ? g_wkh
                        : (mode == 2) ? g_wvh : g_woh;
    const float* bias  = (mode == 0) ? bq : (mode == 1) ? bk
                        : (mode == 2) ? bv : bo;

    const int tid  = threadIdx.x;
    const int lane = tid & 31, wid = tid >> 5;
    const int wm = wid >> 1, wn = wid & 1;
    const int g = lane >> 2, t = lane & 3;
    const int brow = (tile >> 4) * 128;     // 32 row tiles
    const int bcol = (tile & 15) * 128;     // 16 col tiles

    const unsigned lmo = (((lane & 15) * GAP) + (lane >> 4) * 8) * 2;  // bytes

    float acc[2][8][4];
#pragma unroll
    for (int mi = 0; mi < 2; mi++)
#pragma unroll
        for (int nj = 0; nj < 8; nj++)
#pragma unroll
            for (int q = 0; q < 4; q++) acc[mi][nj][q] = 0.f;

    // prologue: buffer 0 (k0 = 0)
#pragma unroll
    for (int l = 0; l < 4; l++) {
        int idx = tid + l * 256;
        int r = idx >> 3, c = (idx & 7) * 8;
        CP16(s2u(&bufA[0][r * GAP + c]), &A[(size_t)(brow + r) * E_ + c]);
        CP16(s2u(&bufB[0][r * GAP + c]), &W[(size_t)(bcol + r) * E_ + c]);
    }
    CP_COMMIT();

    const int KT = E_ / 64;  // 32
    for (int kt = 0; kt < KT; kt++) {
        const int cur = kt & 1;
        CP_WAIT0();
        __syncthreads();
        if (kt + 1 < KT) {
            const int k0 = (kt + 1) * 64;
#pragma unroll
            for (int l = 0; l < 4; l++) {
                int idx = tid + l * 256;
                int r = idx >> 3, c = (idx & 7) * 8;
                CP16(s2u(&bufA[cur ^ 1][r * GAP + c]), &A[(size_t)(brow + r) * E_ + k0 + c]);
                CP16(s2u(&bufB[cur ^ 1][r * GAP + c]), &W[(size_t)(bcol + r) * E_ + k0 + c]);
            }
            CP_COMMIT();
        }

        const unsigned aBase = s2u(bufA[cur]) + (unsigned)(wm * 32 * GAP * 2) + lmo;
        const unsigned bBase = s2u(bufB[cur]) + (unsigned)(wn * 64 * GAP * 2) + lmo;

#pragma unroll
        for (int ks = 0; ks < 4; ks++) {
            const unsigned koff = ks * 32;    // 16 halfs = 32 bytes
            unsigned a[2][4];
            ldm_x4(a[0], aBase + koff);
            ldm_x4(a[1], aBase + 16 * GAP * 2 + koff);
            unsigned bfr[2][4];
            ldm_x4(bfr[0], bBase + koff);
#pragma unroll
            for (int njp = 0; njp < 4; njp++) {
                const int c2 = njp & 1;
                if (njp < 3)
                    ldm_x4(bfr[c2 ^ 1], bBase + (njp + 1) * 16 * GAP * 2 + koff);
                mma_f16(acc[0][2 * njp],     a[0][0], a[0][1], a[0][2], a[0][3], bfr[c2][0], bfr[c2][2]);
                mma_f16(acc[0][2 * njp + 1], a[0][0], a[0][1], a[0][2], a[0][3], bfr[c2][1], bfr[c2][3]);
                mma_f16(acc[1][2 * njp],     a[1][0], a[1][1], a[1][2], a[1][3], bfr[c2][0], bfr[c2][2]);
                mma_f16(acc[1][2 * njp + 1], a[1][0], a[1][1], a[1][2], a[1][3], bfr[c2][1], bfr[c2][3]);
            }
        }
    }
    __syncthreads();

    // epilogue
#pragma unroll
    for (int mi = 0; mi < 2; mi++) {
#pragma unroll
        for (int nj = 0; nj < 8; nj++) {
            int row = brow + wm * 32 + mi * 16 + g;
            int col = bcol + wn * 64 + nj * 8 + 2 * t;
            float b0 = bias[col], b1 = bias[col + 1];
            float v00 = acc[mi][nj][0] + b0, v01 = acc[mi][nj][1] + b1;
            float v10 = acc[mi][nj][2] + b0, v11 = acc[mi][nj][3] + b1;
            if (mode == 0) {
                *(unsigned*)&g_qh[(size_t)row * E_ + col] =
                    h2u(v00 * QSCALE, v01 * QSCALE);
                *(unsigned*)&g_qh[(size_t)(row + 8) * E_ + col] =
                    h2u(v10 * QSCALE, v11 * QSCALE);
            } else if (mode == 4) {
                float2 f0 = { v00, v01 }, f1 = { v10, v11 };
                *(float2*)&outp[(size_t)row * E_ + col]       = f0;
                *(float2*)&outp[(size_t)(row + 8) * E_ + col] = f1;
            } else {
                float* dst   = (mode == 1) ? kc  : vc;
                __half* dstH = (mode == 1) ? g_kh : g_vh;
                int b_i = row >> 10, t_i = row & 1023;
                int h_i = col >> 7,  d_i = col & 127;
                size_t base = ((size_t)(b_i * H_ + h_i) * S_ + TP_ + t_i) * D_ + d_i;
                float2 f0 = { v00, v01 }, f1 = { v10, v11 };
                *(float2*)&dst[base]             = f0;
                *(float2*)&dst[base + 8ull * D_] = f1;
                *(unsigned*)&dstH[base]             = h2u(v00, v01);
                *(unsigned*)&dstH[base + 8ull * D_] = h2u(v10, v11);
            }
        }
    }
}

// ---------------------------------------------------------------------------
// fp16 tensor-core flash attention (round-11 best-known configuration).
// K and V double-buffered in one cp.async group, ONE __syncthreads per chunk.
// P stays in registers.
// ---------------------------------------------------------------------------
#define QPH 136
#define KPH 136
#define VPH 136
#define ATTN_SMEM ((128*QPH + 2*64*KPH + 2*64*VPH) * 2)   // 104448 bytes

__global__ __launch_bounds__(256, 2) void attn_h(void)
{
    extern __shared__ __half sm[];
    __half* sQ = sm;                         // 128 x 136
    __half* sK = sQ + 128 * QPH;             // 2 x 64 x 136
    __half* sV = sK + 2 * 64 * KPH;          // 2 x 64 x 136

    const int qt = blockIdx.x, h = blockIdx.y, b = blockIdx.z;
    const int tid = threadIdx.x, lane = tid & 31, w = tid >> 5;

    const __half* kb = g_kh + (size_t)(b * H_ + h) * S_ * D_;
    const __half* vb = g_vh + (size_t)(b * H_ + h) * S_ * D_;

    // prologue: prefetch K0 + V0 in one group
#pragma unroll
    for (int l = 0; l < 4; l++) {
        int idx = tid + l * 256;
        int r = idx >> 4, c = (idx & 15) * 8;
        CP16(s2u(&sK[r * KPH + c]), &kb[(size_t)r * D_ + c]);
        CP16(s2u(&sV[r * VPH + c]), &vb[(size_t)r * D_ + c]);
    }
    CP_COMMIT();

    // stage Q tile (fp16, already scaled)
#pragma unroll
    for (int l = 0; l < 8; l++) {
        int idx = tid + l * 256;
        int r = idx >> 4, c = (idx & 15) * 8;
        uint4 qv = *(const uint4*)&g_qh[(size_t)(b * T_ + qt * 128 + r) * E_ + h * D_ + c];
        *(uint4*)&sQ[r * QPH + c] = qv;
    }

    float m0 = -1e30f, m1 = -1e30f, l0 = 0.f, l1 = 0.f;
    float acc_o[16][4];
#pragma unroll
    for (int nj = 0; nj < 16; nj++)
#pragma unroll
        for (int q = 0; q < 4; q++) acc_o[nj][q] = 0.f;

    const unsigned lmoQ = (((lane & 15) * QPH) + (lane >> 4) * 8) * 2;
    const unsigned lmoK = (((lane & 15) * KPH) + (lane >> 4) * 8) * 2;
    const unsigned aQBase = s2u(sQ) + (unsigned)(w * 16 * QPH * 2) + lmoQ;

    for (int ci = 0; ci < S_ / 64; ci++) {
        const int cur = ci & 1;
        const unsigned bKBase = s2u(sK + cur * 64 * KPH) + lmoK;
        __half* cV = sV + cur * 64 * VPH;

        CP_WAIT0();
        __syncthreads();   // chunk ci resident; all warps done with ci-1 buffers

        // prefetch K_{ci+1} + V_{ci+1} into the freed buffers
        if (ci + 1 < S_ / 64) {
            const size_t nbase = (size_t)((ci + 1) * 64) * D_;
            __half* nK = sK + (cur ^ 1) * 64 * KPH;
            __half* nV = sV + (cur ^ 1) * 64 * VPH;
#pragma unroll
            for (int l = 0; l < 4; l++) {
                int idx = tid + l * 256;
                int r = idx >> 4, c = (idx & 15) * 8;
                CP16(s2u(&nK[r * KPH + c]), &kb[nbase + (size_t)r * D_ + c]);
                CP16(s2u(&nV[r * VPH + c]), &vb[nbase + (size_t)r * D_ + c]);
            }
            CP_COMMIT();
        }

        // S = Q K^T   (warp: 16 q-rows x 64 keys, 8 k-steps)
        float accs[8][4];
#pragma unroll
        for (int nj = 0; nj < 8; nj++)
#pragma unroll
            for (int q = 0; q < 4; q++) accs[nj][q] = 0.f;

#pragma unroll
        for (int ks = 0; ks < 8; ks++) {
            const unsigned koff = ks * 32;
            unsigned a[4];
            ldm_x4(a, aQBase + koff);
            unsigned bfr[2][4];
            ldm_x4(bfr[0], bKBase + koff);
#pragma unroll
            for (int njp = 0; njp < 4; njp++) {
                const int c2 = njp & 1;
                if (njp < 3)
                    ldm_x4(bfr[c2 ^ 1], bKBase + (njp + 1) * 16 * KPH * 2 + koff);
                mma_f16(accs[2 * njp],     a[0], a[1], a[2], a[3], bfr[c2][0], bfr[c2][2]);
                mma_f16(accs[2 * njp + 1], a[0], a[1], a[2], a[3], bfr[c2][1], bfr[c2][3]);
            }
        }

        // online softmax
        float rm0 = -1e30f, rm1 = -1e30f;
#pragma unroll
        for (int nj = 0; nj < 8; nj++) {
            rm0 = fmaxf(rm0, fmaxf(accs[nj][0], accs[nj][1]));
            rm1 = fmaxf(rm1, fmaxf(accs[nj][2], accs[nj][3]));
        }
        rm0 = fmaxf(rm0, __shfl_xor_sync(0xffffffffu, rm0, 1));
        rm0 = fmaxf(rm0, __shfl_xor_sync(0xffffffffu, rm0, 2));
        rm1 = fmaxf(rm1, __shfl_xor_sync(0xffffffffu, rm1, 1));
        rm1 = fmaxf(rm1, __shfl_xor_sync(0xffffffffu, rm1, 2));

        float nm0 = fmaxf(m0, rm0), nm1 = fmaxf(m1, rm1);
        float al0 = __expf(m0 - nm0), al1 = __expf(m1 - nm1);
        m0 = nm0; m1 = nm1;

        unsigned pA[8], pB[8];
        float sum0 = 0.f, sum1 = 0.f;
#pragma unroll
        for (int nj = 0; nj < 8; nj++) {
            float p0 = __expf(accs[nj][0] - nm0);
            float p1 = __expf(accs[nj][1] - nm0);
            float p2 = __expf(accs[nj][2] - nm1);
            float p3 = __expf(accs[nj][3] - nm1);
            sum0 += p0 + p1;
            sum1 += p2 + p3;
            pA[nj] = h2u(p0, p1);
            pB[nj] = h2u(p2, p3);
        }
        sum0 += __shfl_xor_sync(0xffffffffu, sum0, 1);
        sum0 += __shfl_xor_sync(0xffffffffu, sum0, 2);
        sum1 += __shfl_xor_sync(0xffffffffu, sum1, 1);
        sum1 += __shfl_xor_sync(0xffffffffu, sum1, 2);
        l0 = l0 * al0 + sum0;
        l1 = l1 * al1 + sum1;

        if (!__all_sync(0xffffffffu, (al0 == 1.f) && (al1 == 1.f))) {
#pragma unroll
            for (int nj = 0; nj < 16; nj++) {
                acc_o[nj][0] *= al0; acc_o[nj][1] *= al0;
                acc_o[nj][2] *= al1; acc_o[nj][3] *= al1;
            }
        }

        // O += P V   (V already resident; no extra wait/sync)
#pragma unroll
        for (int ks = 0; ks < 4; ks++) {
            const unsigned a0 = pA[2 * ks],     a1 = pB[2 * ks];
            const unsigned a2 = pA[2 * ks + 1], a3 = pB[2 * ks + 1];
            int key = ks * 16 + (lane & 15);
            unsigned bb[2][4];
            ldm_x4_trans(bb[0], s2u(&cV[key * VPH + (lane >> 4) * 8]));
#pragma unroll
            for (int nj2 = 0; nj2 < 8; nj2++) {
                const int c2 = nj2 & 1;
                if (nj2 < 7) {
                    int dd = (nj2 + 1) * 16 + (lane >> 4) * 8;
                    ldm_x4_trans(bb[c2 ^ 1], s2u(&cV[key * VPH + dd]));
                }
                mma_f16(acc_o[nj2 * 2],     a0, a1, a2, a3, bb[c2][0], bb[c2][1]);
                mma_f16(acc_o[nj2 * 2 + 1], a0, a1, a2, a3, bb[c2][2], bb[c2][3]);
            }
        }
    }

    // epilogue: normalize, write fp16 to g_ah
    const int g = lane >> 2, t = lane & 3;
    float inv0 = 1.f / l0, inv1 = 1.f / l1;
    int row = b * T_ + qt * 128 + w * 16 + g;
#pragma unroll
    for (int nj = 0; nj < 16; nj++) {
        int col = h * D_ + nj * 8 + 2 * t;
        *(unsigned*)&g_ah[(size_t)row * E_ + col] =
            h2u(acc_o[nj][0] * inv0, acc_o[nj][1] * inv0);
        *(unsigned*)&g_ah[(size_t)(row + 8) * E_ + col] =
            h2u(acc_o[nj][2] * inv1, acc_o[nj][3] * inv1);
    }
}

// ---------------------------------------------------------------------------
extern "C" void kernel_launch(void* const* d_in, const int* in_sizes, int n_in,
                              void* d_out, int out_size)
{
    const float* x      = (const float*)d_in[0];
    const float* past_k = (const float*)d_in[1];
    const float* past_v = (const float*)d_in[2];
    const float* Wq     = (const float*)d_in[3];
    const float* bq     = (const float*)d_in[4];
    const float* Wk     = (const float*)d_in[5];
    const float* bk     = (const float*)d_in[6];
    const float* Wv     = (const float*)d_in[7];
    const float* bv     = (const float*)d_in[8];
    const float* Wo     = (const float*)d_in[9];
    const float* bo     = (const float*)d_in[10];

    float* out = (float*)d_out;                       // [B,T,E]
    float* kc  = out + (size_t)NTOK * E_;             // [B,H,S,D]
    float* vc  = kc + (size_t)CACHE_ELEMS;            // [B,H,S,D]

    // fp32 -> fp16 conversions (single launch)
    to_half_all<<<dim3(512, 5), 256>>>(x, Wq, Wk, Wv, Wo);

    cudaFuncSetAttribute(gemm_h, cudaFuncAttributeMaxDynamicSharedMemorySize, GEMM_SMEM);
    cudaFuncSetAttribute(attn_h, cudaFuncAttributeMaxDynamicSharedMemorySize, ATTN_SMEM);

    // fused QKV projections + past-KV copy, INTERLEAVED in a flat 1-D grid:
    // cid&3 -> 0=Q,1=K,2=V,3=copy ; cid>>2 -> tile index (512 tiles each)
    gemm_h<<<2048, 256, GEMM_SMEM>>>(0, bq, bk, bv, bo, past_k, past_v,
                                     kc, vc, out);

    // attention
    attn_h<<<dim3(T_ / 128, H_, B_), 256, ATTN_SMEM>>>();

    // output projection (flat grid of 512 tiles, mode 4)
    gemm_h<<<512, 256, GEMM_SMEM>>>(4, bq, bk, bv, bo, past_k, past_v,
                                    kc, vc, out);
}